// round 3
// baseline (speedup 1.0000x reference)
#include <cuda_runtime.h>
#include <math_constants.h>
#include <cstdint>

#define BN 4
#define TT 512
#define SS 512
#define IND 512
#define MD 256

// Scratch (allocation-free rule: __device__ globals)
__device__ float g_wq[BN * TT * MD];      // [b*T+t][d]
__device__ float g_uht[BN * MD * SS];     // [b][d][s]  (transposed uh)
__device__ float g_c[BN * TT * MD];       // [b*T+t][m]
__device__ float g_align_scratch[BN * TT * SS];

__device__ __forceinline__ float tanhap(float x) {
    float y;
    asm("tanh.approx.f32 %0, %1;" : "=f"(y) : "f"(x));
    return y;
}

__device__ __forceinline__ uint32_t tf32_rna(float x) {
    uint32_t r;
    asm("cvt.rna.tf32.f32 %0, %1;" : "=r"(r) : "f"(x));
    return r;
}

__device__ __forceinline__ void mma_tf32(
    float& c0, float& c1, float& c2, float& c3,
    uint32_t a0, uint32_t a1, uint32_t a2, uint32_t a3,
    uint32_t b0, uint32_t b1)
{
    asm("mma.sync.aligned.m16n8k8.row.col.f32.tf32.tf32.f32 "
        "{%0,%1,%2,%3},{%4,%5,%6,%7},{%8,%9},{%0,%1,%2,%3};"
        : "+f"(c0), "+f"(c1), "+f"(c2), "+f"(c3)
        : "r"(a0), "r"(a1), "r"(a2), "r"(a3), "r"(b0), "r"(b1));
}

// ---------------------------------------------------------------------------
// gemm_tc<MODE,KDIM>: C[M,N] = A[M,KDIM] @ B[N,KDIM]^T  via tf32x3 mma.sync.
// Block tile 64x64, 128 threads (4 warps, 2x2), warp tile 32x32.
// Smem holds (hi,lo) pairs in mma fragment order (float4-loadable).
// MODE 0: A=A0 (stride 512), C -> Cout (g_wq, stride 256)
// MODE 1: A=A0 (stride 256), C+bias -> g_uht transposed [b][col][s]
// MODE 2: A=concat(A0 row[0:256), A1 row[0:512)), C+bias -> Cout (stride 512)
// ---------------------------------------------------------------------------
template <int MODE, int KDIM>
__global__ __launch_bounds__(128) void gemm_tc(
    const float* __restrict__ A0, const float* __restrict__ A1,
    const float* __restrict__ Bw, const float* __restrict__ bias,
    float* __restrict__ Cout)
{
    // [buf][kstep][tile][lane][slot][hi/lo]
    __shared__ float Ash[2][2][4][32][4][2];
    __shared__ float Bsh[2][2][8][32][2][2];

    const int tid = threadIdx.x;
    const int lane = tid & 31;
    const int warp = tid >> 5;
    const int mw = warp >> 1, nw = warp & 1;
    const int bm = blockIdx.y * 64;
    const int bn = blockIdx.x * 64;

    auto fetchA = [&](int grow, int c) -> float4 {
        if (MODE == 2) {
            if (c < 256) return *(const float4*)(A0 + grow * 256 + c);
            return *(const float4*)(A1 + grow * 512 + (c - 256));
        }
        return *(const float4*)(A0 + grow * KDIM + c);
    };

    float4 ra[2], rb[2];
    auto ldTile = [&](int k0) {
#pragma unroll
        for (int u = 0; u < 2; u++) {
            const int i = tid + u * 128;
            const int row = i >> 2, c4 = (i & 3) << 2;
            ra[u] = fetchA(bm + row, k0 + c4);
            rb[u] = *(const float4*)(Bw + (bn + row) * KDIM + k0 + c4);
        }
    };
    auto stTile = [&](int b2) {
#pragma unroll
        for (int u = 0; u < 2; u++) {
            const int i = tid + u * 128;
            const int row = i >> 2, c4 = (i & 3) << 2;
            float vA[4] = {ra[u].x, ra[u].y, ra[u].z, ra[u].w};
            float vB[4] = {rb[u].x, rb[u].y, rb[u].z, rb[u].w};
#pragma unroll
            for (int j = 0; j < 4; j++) {
                const int c = c4 + j, ks = c >> 3, cc = c & 7;
                {
                    const int mt = row >> 4, r = row & 15;
                    const int ln = ((r & 7) << 2) | (cc & 3);
                    const int sl = (r >> 3) | ((cc >> 2) << 1);
                    const uint32_t hi = tf32_rna(vA[j]);
                    const uint32_t lo = tf32_rna(vA[j] - __uint_as_float(hi));
                    Ash[b2][ks][mt][ln][sl][0] = __uint_as_float(hi);
                    Ash[b2][ks][mt][ln][sl][1] = __uint_as_float(lo);
                }
                {
                    const int nt = row >> 3, n = row & 7;
                    const int ln = (n << 2) | (cc & 3);
                    const int sl = cc >> 2;
                    const uint32_t hi = tf32_rna(vB[j]);
                    const uint32_t lo = tf32_rna(vB[j] - __uint_as_float(hi));
                    Bsh[b2][ks][nt][ln][sl][0] = __uint_as_float(hi);
                    Bsh[b2][ks][nt][ln][sl][1] = __uint_as_float(lo);
                }
            }
        }
    };

    float c[2][4][4];
#pragma unroll
    for (int m2 = 0; m2 < 2; m2++)
#pragma unroll
        for (int n2 = 0; n2 < 4; n2++)
#pragma unroll
            for (int q = 0; q < 4; q++) c[m2][n2][q] = 0.f;

    ldTile(0);
    stTile(0);
    __syncthreads();

    const int NBK = KDIM / 16;
    int buf = 0;
    for (int bk = 0; bk < NBK; bk++) {
        const bool more = (bk + 1 < NBK);
        if (more) ldTile((bk + 1) * 16);

#pragma unroll
        for (int ks = 0; ks < 2; ks++) {
            float4 aA[2][2];
#pragma unroll
            for (int m2 = 0; m2 < 2; m2++) {
                const float* p = &Ash[buf][ks][mw * 2 + m2][lane][0][0];
                aA[m2][0] = *(const float4*)p;
                aA[m2][1] = *(const float4*)(p + 4);
            }
            float4 bB[4];
#pragma unroll
            for (int n2 = 0; n2 < 4; n2++)
                bB[n2] = *(const float4*)&Bsh[buf][ks][nw * 4 + n2][lane][0][0];

#pragma unroll
            for (int m2 = 0; m2 < 2; m2++) {
                const uint32_t ah0 = __float_as_uint(aA[m2][0].x);
                const uint32_t al0 = __float_as_uint(aA[m2][0].y);
                const uint32_t ah1 = __float_as_uint(aA[m2][0].z);
                const uint32_t al1 = __float_as_uint(aA[m2][0].w);
                const uint32_t ah2 = __float_as_uint(aA[m2][1].x);
                const uint32_t al2 = __float_as_uint(aA[m2][1].y);
                const uint32_t ah3 = __float_as_uint(aA[m2][1].z);
                const uint32_t al3 = __float_as_uint(aA[m2][1].w);
#pragma unroll
                for (int n2 = 0; n2 < 4; n2++) {
                    const uint32_t bh0 = __float_as_uint(bB[n2].x);
                    const uint32_t bl0 = __float_as_uint(bB[n2].y);
                    const uint32_t bh1 = __float_as_uint(bB[n2].z);
                    const uint32_t bl1 = __float_as_uint(bB[n2].w);
                    float* cc = c[m2][n2];
                    mma_tf32(cc[0], cc[1], cc[2], cc[3], ah0, ah1, ah2, ah3, bh0, bh1);
                    mma_tf32(cc[0], cc[1], cc[2], cc[3], al0, al1, al2, al3, bh0, bh1);
                    mma_tf32(cc[0], cc[1], cc[2], cc[3], ah0, ah1, ah2, ah3, bl0, bl1);
                }
            }
        }
        if (more) stTile(buf ^ 1);
        __syncthreads();
        buf ^= 1;
    }

    // Writeback. c0:(g,2tg) c1:(g,2tg+1) c2:(g+8,2tg) c3:(g+8,2tg+1)
    const int g = lane >> 2, tg = lane & 3;
#pragma unroll
    for (int m2 = 0; m2 < 2; m2++) {
        const int row0 = bm + mw * 32 + m2 * 16 + g;
#pragma unroll
        for (int n2 = 0; n2 < 4; n2++) {
            const int col = bn + nw * 32 + n2 * 8 + tg * 2;
            float* cc = c[m2][n2];
            if (MODE == 0) {
                *(float2*)&Cout[row0 * MD + col] = make_float2(cc[0], cc[1]);
                *(float2*)&Cout[(row0 + 8) * MD + col] = make_float2(cc[2], cc[3]);
            } else if (MODE == 1) {
                const float b0v = bias[col], b1v = bias[col + 1];
                const int b_ = row0 >> 9;
                const int s0 = row0 & 511, s1 = (row0 + 8) & 511;
                float* base = g_uht + b_ * (MD * SS);
                base[col * SS + s0] = cc[0] + b0v;
                base[(col + 1) * SS + s0] = cc[1] + b1v;
                base[col * SS + s1] = cc[2] + b0v;
                base[(col + 1) * SS + s1] = cc[3] + b1v;
            } else {
                const float b0v = bias[col], b1v = bias[col + 1];
                *(float2*)&Cout[row0 * IND + col] =
                    make_float2(cc[0] + b0v, cc[1] + b1v);
                *(float2*)&Cout[(row0 + 8) * IND + col] =
                    make_float2(cc[2] + b0v, cc[3] + b1v);
            }
        }
    }
}

// ---------------------------------------------------------------------------
// align_kernel: grid (s-chunk, t-tile, b). One 128-s chunk x 16-t per block.
// Early-exits on fully-masked chunks (load balance). Writes RAW scores.
// ---------------------------------------------------------------------------
__global__ __launch_bounds__(256) void align_kernel(
    const int* __restrict__ mem_masks, const float* __restrict__ v,
    float* __restrict__ pa)
{
    const int b = blockIdx.z;
    const int t0 = blockIdx.y * 16;
    const int c = blockIdx.x;
    const int len = mem_masks[b];
    if (c * 128 >= len) return;

    extern __shared__ float sh[];
    float* uh_sh = sh;                 // [256][128]
    float* wq_sh = sh + 256 * 128;     // [16][256]
    float* v_sh  = wq_sh + 16 * 256;   // [256]

    const int tid = threadIdx.x;
    const int lane = tid & 31;
    const int warp = tid >> 5;

    {
        const float* src = g_wq + (b * TT + t0) * MD;
        for (int i = tid; i < (16 * 256) / 4; i += 256)
            *(float4*)&wq_sh[i * 4] = *(const float4*)&src[i * 4];
        if (tid < 64)
            *(float4*)&v_sh[tid * 4] = *(const float4*)&v[tid * 4];
        const float* usrc = g_uht + b * (MD * SS) + c * 128;
        for (int i = tid; i < 256 * 32; i += 256) {
            const int d = i >> 5, g = i & 31;
            *(float4*)&uh_sh[d * 128 + g * 4] =
                *(const float4*)&usrc[d * SS + g * 4];
        }
    }
    __syncthreads();

    const int ta = warp * 2;
    const float* wq0 = wq_sh + ta * 256;
    const float* wq1 = wq0 + 256;
    const int sl = lane * 4;
    float4 a0 = make_float4(0.f, 0.f, 0.f, 0.f);
    float4 a1 = make_float4(0.f, 0.f, 0.f, 0.f);
#pragma unroll 4
    for (int d = 0; d < 256; d++) {
        float4 u = *(float4*)&uh_sh[d * 128 + sl];
        float w0 = wq0[d], w1 = wq1[d], vd = v_sh[d];
        a0.x += vd * tanhap(u.x + w0);
        a0.y += vd * tanhap(u.y + w0);
        a0.z += vd * tanhap(u.z + w0);
        a0.w += vd * tanhap(u.w + w0);
        a1.x += vd * tanhap(u.x + w1);
        a1.y += vd * tanhap(u.y + w1);
        a1.z += vd * tanhap(u.z + w1);
        a1.w += vd * tanhap(u.w + w1);
    }
    const int sg = c * 128 + sl;
    *(float4*)&pa[(b * TT + t0 + ta) * SS + sg] = a0;
    *(float4*)&pa[(b * TT + t0 + ta + 1) * SS + sg] = a1;
}

// ---------------------------------------------------------------------------
// softctx_kernel: masked softmax + context GEMM per (b, 16-t tile).
// ---------------------------------------------------------------------------
__global__ __launch_bounds__(256) void softctx_kernel(
    const float* __restrict__ mems, const int* __restrict__ mem_masks,
    float* __restrict__ pa)
{
    extern __shared__ float sh[];
    float* mem_sh = sh;                // [128][256]
    float* al_sh  = sh + 128 * 256;    // [16][512]

    const int tid = threadIdx.x;
    const int lane = tid & 31;
    const int warp = tid >> 5;
    const int b = blockIdx.x >> 5;
    const int t0 = (blockIdx.x & 31) * 16;
    const int len = mem_masks[b];
    const float NEG = -CUDART_INF_F;

    for (int i = tid; i < 16 * 512; i += 256) {
        const int t = i >> 9, s = i & 511;
        al_sh[i] = (s < len) ? pa[(b * TT + t0 + t) * SS + s] : NEG;
    }
    __syncthreads();

    for (int r = 0; r < 2; r++) {
        const int t = warp * 2 + r;
        float* row = al_sh + t * 512;
        float mx = NEG;
#pragma unroll
        for (int k = 0; k < 16; k++) mx = fmaxf(mx, row[lane + k * 32]);
#pragma unroll
        for (int o = 16; o; o >>= 1) mx = fmaxf(mx, __shfl_xor_sync(~0u, mx, o));
        float e[16];
        float sum = 0.f;
#pragma unroll
        for (int k = 0; k < 16; k++) {
            const int s = lane + k * 32;
            const float val = (s < len) ? __expf(row[s] - mx) : 0.f;
            e[k] = val;
            sum += val;
        }
#pragma unroll
        for (int o = 16; o; o >>= 1) sum += __shfl_xor_sync(~0u, sum, o);
        const float inv = 1.0f / sum;
#pragma unroll
        for (int k = 0; k < 16; k++) {
            const int s = lane + k * 32;
            const float p = e[k] * inv;
            row[s] = p;
            pa[(b * TT + t0 + t) * SS + s] = p;
        }
    }

    float cc[4][4];
#pragma unroll
    for (int i = 0; i < 4; i++)
#pragma unroll
        for (int j = 0; j < 4; j++) cc[i][j] = 0.f;

    const int tq = (tid >> 6) * 4;
    const int m0 = (tid & 63) * 4;
    const int nch = (len + 127) >> 7;

    for (int c = 0; c < nch; c++) {
        __syncthreads();
        {
            const float* src = mems + b * (SS * MD) + c * 128 * MD;
            for (int i = tid; i < (128 * 256) / 4; i += 256)
                *(float4*)&mem_sh[i * 4] = *(const float4*)&src[i * 4];
        }
        __syncthreads();
#pragma unroll 2
        for (int s2 = 0; s2 < 128; s2++) {
            float4 mm = *(float4*)&mem_sh[s2 * 256 + m0];
            const int s = c * 128 + s2;
            const float p0 = al_sh[(tq + 0) * 512 + s];
            const float p1 = al_sh[(tq + 1) * 512 + s];
            const float p2 = al_sh[(tq + 2) * 512 + s];
            const float p3 = al_sh[(tq + 3) * 512 + s];
            cc[0][0] += p0 * mm.x; cc[0][1] += p0 * mm.y;
            cc[0][2] += p0 * mm.z; cc[0][3] += p0 * mm.w;
            cc[1][0] += p1 * mm.x; cc[1][1] += p1 * mm.y;
            cc[1][2] += p1 * mm.z; cc[1][3] += p1 * mm.w;
            cc[2][0] += p2 * mm.x; cc[2][1] += p2 * mm.y;
            cc[2][2] += p2 * mm.z; cc[2][3] += p2 * mm.w;
            cc[3][0] += p3 * mm.x; cc[3][1] += p3 * mm.y;
            cc[3][2] += p3 * mm.z; cc[3][3] += p3 * mm.w;
        }
    }
#pragma unroll
    for (int i = 0; i < 4; i++) {
        float4 r = make_float4(cc[i][0], cc[i][1], cc[i][2], cc[i][3]);
        *(float4*)&g_c[(b * TT + t0 + tq + i) * MD + m0] = r;
    }
}

// ---------------------------------------------------------------------------
extern "C" void kernel_launch(void* const* d_in, const int* in_sizes, int n_in,
                              void* d_out, int out_size)
{
    const float* inputs    = (const float*)d_in[0];
    const float* mems      = (const float*)d_in[1];
    const int*   mem_masks = (const int*)d_in[2];
    const float* Wq        = (const float*)d_in[3];
    const float* Wc        = (const float*)d_in[4];
    const float* bc        = (const float*)d_in[5];
    const float* v         = (const float*)d_in[6];
    const float* Wout      = (const float*)d_in[7];
    const float* bout      = (const float*)d_in[8];

    float* out = (float*)d_out;
    float* pa;
    if (out_size >= BN * TT * IND + BN * TT * SS) {
        pa = out + BN * TT * IND;  // align written in-place in the output
    } else {
        cudaGetSymbolAddress((void**)&pa, g_align_scratch);
    }

    float* g_c_ptr;
    cudaGetSymbolAddress((void**)&g_c_ptr, g_c);
    float* g_wq_ptr;
    cudaGetSymbolAddress((void**)&g_wq_ptr, g_wq);

    const size_t SMEM_ALIGN = (size_t)(256 * 128 + 16 * 256 + 256) * sizeof(float);
    const size_t SMEM_SOFT  = (size_t)(128 * 256 + 16 * 512) * sizeof(float);
    cudaFuncSetAttribute(align_kernel,
                         cudaFuncAttributeMaxDynamicSharedMemorySize, (int)SMEM_ALIGN);
    cudaFuncSetAttribute(softctx_kernel,
                         cudaFuncAttributeMaxDynamicSharedMemorySize, (int)SMEM_SOFT);

    // wq = inputs @ Wq^T        [2048 x 256], K=512
    gemm_tc<0, 512><<<dim3(MD / 64, 2048 / 64), 128>>>(
        inputs, nullptr, Wq, nullptr, g_wq_ptr);
    // uht = (mems @ Wc^T + bc) transposed   [b][d][s], K=256
    gemm_tc<1, 256><<<dim3(MD / 64, 2048 / 64), 128>>>(
        mems, nullptr, Wc, bc, nullptr);
    align_kernel<<<dim3(4, 32, 4), 256, SMEM_ALIGN>>>(mem_masks, v, pa);
    softctx_kernel<<<128, 256, SMEM_SOFT>>>(mems, mem_masks, pa);
    // attn_h = concat(c, inputs) @ Wout^T + bout  [2048 x 512], K=768
    gemm_tc<2, 768><<<dim3(IND / 64, 2048 / 64), 128>>>(
        g_c_ptr, inputs, Wout, bout, out);
}

// round 4
// speedup vs baseline: 1.2847x; 1.2847x over previous
#include <cuda_runtime.h>
#include <math_constants.h>

#define BN 4
#define TT 512
#define SS 512
#define IND 512
#define MD 256

// Scratch (allocation-free rule: __device__ globals)
__device__ float g_wq[BN * TT * MD];      // [b*T+t][d]
__device__ float g_uht[BN * MD * SS];     // [b][d][s]  (transposed uh)
__device__ float g_c[BN * TT * MD];       // [b*T+t][m]
__device__ float g_partial[3][BN * TT * IND];  // out split-K partials
__device__ float g_align_scratch[BN * TT * SS];

__device__ __forceinline__ float tanhap(float x) {
    float y;
    asm("tanh.approx.f32 %0, %1;" : "=f"(y) : "f"(x));
    return y;
}

// ---------------------------------------------------------------------------
// proj_kernel (R1, measured 44us): z=0 -> g_wq = inputs @ Wq^T   (K=512)
//              z=1 -> g_uht[b][n][s] = mems @ Wc^T + bc, transposed (K=256)
// 128x64 block tile, 256 threads, 8x4 per thread, TK=8, register prefetch.
// ---------------------------------------------------------------------------
__global__ __launch_bounds__(256) void proj_kernel(
    const float* __restrict__ inputs, const float* __restrict__ mems,
    const float* __restrict__ Wq, const float* __restrict__ Wc,
    const float* __restrict__ bc)
{
    const int z = blockIdx.z;
    const float* A  = z ? mems : inputs;
    const float* Bm = z ? Wc : Wq;
    const int K = z ? MD : IND;

    __shared__ float As[8][132];
    __shared__ float Bs[8][68];

    const int tid = threadIdx.x;
    const int bm = blockIdx.y * 128;
    const int bn = blockIdx.x * 64;
    const int lrA = tid >> 1;
    const int lcA = (tid & 1) * 4;
    const int tx = tid & 15, ty = tid >> 4;
    const int n0 = tx * 4, m0 = ty * 8;

    float acc[8][4];
#pragma unroll
    for (int i = 0; i < 8; i++)
#pragma unroll
        for (int j = 0; j < 4; j++) acc[i][j] = 0.f;

    float4 a4 = *(const float4*)(A + (bm + lrA) * K + lcA);
    float4 b4 = make_float4(0.f, 0.f, 0.f, 0.f);
    if (tid < 128) b4 = *(const float4*)(Bm + (bn + lrA) * K + lcA);

    for (int k0 = 0; k0 < K; k0 += 8) {
        As[lcA + 0][lrA] = a4.x; As[lcA + 1][lrA] = a4.y;
        As[lcA + 2][lrA] = a4.z; As[lcA + 3][lrA] = a4.w;
        if (tid < 128) {
            Bs[lcA + 0][lrA] = b4.x; Bs[lcA + 1][lrA] = b4.y;
            Bs[lcA + 2][lrA] = b4.z; Bs[lcA + 3][lrA] = b4.w;
        }
        __syncthreads();
        const int kn = k0 + 8;
        if (kn < K) {
            a4 = *(const float4*)(A + (bm + lrA) * K + kn + lcA);
            if (tid < 128) b4 = *(const float4*)(Bm + (bn + lrA) * K + kn + lcA);
        }
#pragma unroll
        for (int kk = 0; kk < 8; kk++) {
            float4 x0 = *(const float4*)&As[kk][m0];
            float4 x1 = *(const float4*)&As[kk][m0 + 4];
            float4 y  = *(const float4*)&Bs[kk][n0];
            float am[8] = {x0.x, x0.y, x0.z, x0.w, x1.x, x1.y, x1.z, x1.w};
            float bb[4] = {y.x, y.y, y.z, y.w};
#pragma unroll
            for (int i = 0; i < 8; i++)
#pragma unroll
                for (int j = 0; j < 4; j++) acc[i][j] += am[i] * bb[j];
        }
        __syncthreads();
    }

    if (z == 0) {
#pragma unroll
        for (int i = 0; i < 8; i++) {
            float4 r = make_float4(acc[i][0], acc[i][1], acc[i][2], acc[i][3]);
            *(float4*)&g_wq[(bm + m0 + i) * MD + bn + n0] = r;
        }
    } else {
        float bb[4];
#pragma unroll
        for (int j = 0; j < 4; j++) bb[j] = bc[bn + n0 + j];
#pragma unroll
        for (int i = 0; i < 8; i++) {
            const int m = bm + m0 + i;
            const int b = m >> 9;
            const int s = m & 511;
#pragma unroll
            for (int j = 0; j < 4; j++)
                g_uht[b * (MD * SS) + (bn + n0 + j) * SS + s] = acc[i][j] + bb[j];
        }
    }
}

// ---------------------------------------------------------------------------
// align_kernel (R2/R3, works): grid (s-chunk, t-tile, b). Early-exit on
// fully-masked chunks. Writes RAW scores to pa.
// ---------------------------------------------------------------------------
__global__ __launch_bounds__(256) void align_kernel(
    const int* __restrict__ mem_masks, const float* __restrict__ v,
    float* __restrict__ pa)
{
    const int b = blockIdx.z;
    const int t0 = blockIdx.y * 16;
    const int c = blockIdx.x;
    const int len = mem_masks[b];
    if (c * 128 >= len) return;

    extern __shared__ float sh[];
    float* uh_sh = sh;                 // [256][128]
    float* wq_sh = sh + 256 * 128;     // [16][256]
    float* v_sh  = wq_sh + 16 * 256;   // [256]

    const int tid = threadIdx.x;
    const int lane = tid & 31;
    const int warp = tid >> 5;

    {
        const float* src = g_wq + (b * TT + t0) * MD;
        for (int i = tid; i < (16 * 256) / 4; i += 256)
            *(float4*)&wq_sh[i * 4] = *(const float4*)&src[i * 4];
        if (tid < 64)
            *(float4*)&v_sh[tid * 4] = *(const float4*)&v[tid * 4];
        const float* usrc = g_uht + b * (MD * SS) + c * 128;
        for (int i = tid; i < 256 * 32; i += 256) {
            const int d = i >> 5, g = i & 31;
            *(float4*)&uh_sh[d * 128 + g * 4] =
                *(const float4*)&usrc[d * SS + g * 4];
        }
    }
    __syncthreads();

    const int ta = warp * 2;
    const float* wq0 = wq_sh + ta * 256;
    const float* wq1 = wq0 + 256;
    const int sl = lane * 4;
    float4 a0 = make_float4(0.f, 0.f, 0.f, 0.f);
    float4 a1 = make_float4(0.f, 0.f, 0.f, 0.f);
#pragma unroll 4
    for (int d = 0; d < 256; d++) {
        float4 u = *(float4*)&uh_sh[d * 128 + sl];
        float w0 = wq0[d], w1 = wq1[d], vd = v_sh[d];
        a0.x += vd * tanhap(u.x + w0);
        a0.y += vd * tanhap(u.y + w0);
        a0.z += vd * tanhap(u.z + w0);
        a0.w += vd * tanhap(u.w + w0);
        a1.x += vd * tanhap(u.x + w1);
        a1.y += vd * tanhap(u.y + w1);
        a1.z += vd * tanhap(u.z + w1);
        a1.w += vd * tanhap(u.w + w1);
    }
    const int sg = c * 128 + sl;
    *(float4*)&pa[(b * TT + t0 + ta) * SS + sg] = a0;
    *(float4*)&pa[(b * TT + t0 + ta + 1) * SS + sg] = a1;
}

// ---------------------------------------------------------------------------
// softmax_kernel: warp per t-row, 8 rows/block, 256 blocks.
// Reads raw scores (masked by len), writes probabilities to all 512 cols.
// ---------------------------------------------------------------------------
__global__ __launch_bounds__(256) void softmax_kernel(
    const int* __restrict__ mem_masks, float* __restrict__ pa)
{
    const int lane = threadIdx.x & 31;
    const int warp = threadIdx.x >> 5;
    const int row = blockIdx.x * 8 + warp;   // 0..2047
    const int b = row >> 9;
    const int len = mem_masks[b];
    float* prow = pa + row * SS;
    const float NEG = -CUDART_INF_F;

    float vals[16];
    float mx = NEG;
#pragma unroll
    for (int k = 0; k < 16; k++) {
        const int s = lane + k * 32;
        const float val = (s < len) ? prow[s] : NEG;
        vals[k] = val;
        mx = fmaxf(mx, val);
    }
#pragma unroll
    for (int o = 16; o; o >>= 1) mx = fmaxf(mx, __shfl_xor_sync(~0u, mx, o));
    float sum = 0.f;
#pragma unroll
    for (int k = 0; k < 16; k++) {
        const int s = lane + k * 32;
        const float e = (s < len) ? __expf(vals[k] - mx) : 0.f;
        vals[k] = e;
        sum += e;
    }
#pragma unroll
    for (int o = 16; o; o >>= 1) sum += __shfl_xor_sync(~0u, sum, o);
    const float inv = 1.0f / sum;
#pragma unroll
    for (int k = 0; k < 16; k++) prow[lane + k * 32] = vals[k] * inv;
}

// ---------------------------------------------------------------------------
// ctx_kernel: per-b GEMM  c[t][m] = sum_s P[t][s] * mems[b][s][m].
// No transposes needed: P rows are s-contiguous (-> As[k][t] scatter),
// mems rows are m-contiguous (-> Bs[k][m] direct). K trimmed to ceil(len/8)
// (P is exactly 0 beyond len). 64x64 tile, 128 threads, 8x4 per thread.
// ---------------------------------------------------------------------------
__global__ __launch_bounds__(128) void ctx_kernel(
    const float* __restrict__ mems, const int* __restrict__ mem_masks,
    const float* __restrict__ pa)
{
    __shared__ float As[8][68];   // [k][t]
    __shared__ float Bs[8][68];   // [k][m]

    const int b = blockIdx.z;
    const int t0 = blockIdx.y * 64;
    const int n0b = blockIdx.x * 64;
    const int len = mem_masks[b];
    const int NT = (len + 7) >> 3;

    const float* P  = pa + (b * TT + t0) * SS;
    const float* Mb = mems + b * (SS * MD) + n0b;

    const int tid = threadIdx.x;
    const int lrA = tid >> 1;            // t row 0..63
    const int lcA = (tid & 1) * 4;       // k 0 or 4
    const int krB = tid >> 4;            // k 0..7
    const int mcB = (tid & 15) * 4;      // m 0..60
    const int tx = tid & 15, ty = tid >> 4;
    const int n0 = tx * 4, m0 = ty * 8;

    float acc[8][4];
#pragma unroll
    for (int i = 0; i < 8; i++)
#pragma unroll
        for (int j = 0; j < 4; j++) acc[i][j] = 0.f;

    float4 a4 = *(const float4*)(P + lrA * SS + lcA);
    float4 b4 = *(const float4*)(Mb + krB * MD + mcB);

    for (int kt = 0; kt < NT; kt++) {
        As[lcA + 0][lrA] = a4.x; As[lcA + 1][lrA] = a4.y;
        As[lcA + 2][lrA] = a4.z; As[lcA + 3][lrA] = a4.w;
        Bs[krB][mcB + 0] = b4.x; Bs[krB][mcB + 1] = b4.y;
        Bs[krB][mcB + 2] = b4.z; Bs[krB][mcB + 3] = b4.w;
        __syncthreads();
        if (kt + 1 < NT) {
            const int kn = (kt + 1) * 8;
            a4 = *(const float4*)(P + lrA * SS + kn + lcA);
            b4 = *(const float4*)(Mb + (kn + krB) * MD + mcB);
        }
#pragma unroll
        for (int kk = 0; kk < 8; kk++) {
            float4 x0 = *(const float4*)&As[kk][m0];
            float4 x1 = *(const float4*)&As[kk][m0 + 4];
            float4 y  = *(const float4*)&Bs[kk][n0];
            float am[8] = {x0.x, x0.y, x0.z, x0.w, x1.x, x1.y, x1.z, x1.w};
            float bb[4] = {y.x, y.y, y.z, y.w};
#pragma unroll
            for (int i = 0; i < 8; i++)
#pragma unroll
                for (int j = 0; j < 4; j++) acc[i][j] += am[i] * bb[j];
        }
        __syncthreads();
    }

#pragma unroll
    for (int i = 0; i < 8; i++) {
        float4 r = make_float4(acc[i][0], acc[i][1], acc[i][2], acc[i][3]);
        *(float4*)&g_c[(b * TT + t0 + m0 + i) * MD + n0b + n0] = r;
    }
}

// ---------------------------------------------------------------------------
// out_kernel: split-K=3 partials of attn_h = concat(c, inputs) @ Wout^T.
// K chunk 256; kc=0 reads g_c (stride 256), kc=1/2 read inputs halves
// (stride 512). 128x64 tile, 256 threads. Writes g_partial[kc].
// ---------------------------------------------------------------------------
__global__ __launch_bounds__(256) void out_kernel(
    const float* __restrict__ inputs, const float* __restrict__ Wout)
{
    __shared__ float As[8][132];
    __shared__ float Bs[8][68];

    const int tid = threadIdx.x;
    const int bm = blockIdx.y * 128;
    const int bn = blockIdx.x * 64;
    const int kc = blockIdx.z;
    const int lrA = tid >> 1;
    const int lcA = (tid & 1) * 4;
    const int tx = tid & 15, ty = tid >> 4;
    const int n0 = tx * 4, m0 = ty * 8;

    const float* Abase = (kc == 0) ? (g_c + (bm + lrA) * MD)
                                   : (inputs + (bm + lrA) * IND + (kc - 1) * 256);
    const float* Wbase = Wout + (bn + lrA) * 768 + kc * 256;

    float acc[8][4];
#pragma unroll
    for (int i = 0; i < 8; i++)
#pragma unroll
        for (int j = 0; j < 4; j++) acc[i][j] = 0.f;

    float4 a4 = *(const float4*)(Abase + lcA);
    float4 b4 = make_float4(0.f, 0.f, 0.f, 0.f);
    if (tid < 128) b4 = *(const float4*)(Wbase + lcA);

    for (int k0 = 0; k0 < 256; k0 += 8) {
        As[lcA + 0][lrA] = a4.x; As[lcA + 1][lrA] = a4.y;
        As[lcA + 2][lrA] = a4.z; As[lcA + 3][lrA] = a4.w;
        if (tid < 128) {
            Bs[lcA + 0][lrA] = b4.x; Bs[lcA + 1][lrA] = b4.y;
            Bs[lcA + 2][lrA] = b4.z; Bs[lcA + 3][lrA] = b4.w;
        }
        __syncthreads();
        const int kn = k0 + 8;
        if (kn < 256) {
            a4 = *(const float4*)(Abase + kn + lcA);
            if (tid < 128) b4 = *(const float4*)(Wbase + kn + lcA);
        }
#pragma unroll
        for (int kk = 0; kk < 8; kk++) {
            float4 x0 = *(const float4*)&As[kk][m0];
            float4 x1 = *(const float4*)&As[kk][m0 + 4];
            float4 y  = *(const float4*)&Bs[kk][n0];
            float am[8] = {x0.x, x0.y, x0.z, x0.w, x1.x, x1.y, x1.z, x1.w};
            float bb[4] = {y.x, y.y, y.z, y.w};
#pragma unroll
            for (int i = 0; i < 8; i++)
#pragma unroll
                for (int j = 0; j < 4; j++) acc[i][j] += am[i] * bb[j];
        }
        __syncthreads();
    }

    float* dst = g_partial[kc];
#pragma unroll
    for (int i = 0; i < 8; i++) {
        float4 r = make_float4(acc[i][0], acc[i][1], acc[i][2], acc[i][3]);
        *(float4*)&dst[(bm + m0 + i) * IND + bn + n0] = r;
    }
}

// ---------------------------------------------------------------------------
// reduce_kernel: out = partial0 + partial1 + partial2 + bias
// ---------------------------------------------------------------------------
__global__ __launch_bounds__(256) void reduce_kernel(
    const float* __restrict__ bout, float* __restrict__ out)
{
    const int idx = blockIdx.x * 256 + threadIdx.x;   // float4 index
    const int e = idx * 4;
    float4 p0 = *(const float4*)&g_partial[0][e];
    float4 p1 = *(const float4*)&g_partial[1][e];
    float4 p2 = *(const float4*)&g_partial[2][e];
    float4 bb = *(const float4*)&bout[e & 511];
    float4 r = make_float4(p0.x + p1.x + p2.x + bb.x,
                           p0.y + p1.y + p2.y + bb.y,
                           p0.z + p1.z + p2.z + bb.z,
                           p0.w + p1.w + p2.w + bb.w);
    *(float4*)&out[e] = r;
}

// ---------------------------------------------------------------------------
extern "C" void kernel_launch(void* const* d_in, const int* in_sizes, int n_in,
                              void* d_out, int out_size)
{
    const float* inputs    = (const float*)d_in[0];
    const float* mems      = (const float*)d_in[1];
    const int*   mem_masks = (const int*)d_in[2];
    const float* Wq        = (const float*)d_in[3];
    const float* Wc        = (const float*)d_in[4];
    const float* bc        = (const float*)d_in[5];
    const float* v         = (const float*)d_in[6];
    const float* Wout      = (const float*)d_in[7];
    const float* bout      = (const float*)d_in[8];

    float* out = (float*)d_out;
    float* pa;
    if (out_size >= BN * TT * IND + BN * TT * SS) {
        pa = out + BN * TT * IND;  // align written in-place in the output
    } else {
        cudaGetSymbolAddress((void**)&pa, g_align_scratch);
    }

    const size_t SMEM_ALIGN = (size_t)(256 * 128 + 16 * 256 + 256) * sizeof(float);
    cudaFuncSetAttribute(align_kernel,
                         cudaFuncAttributeMaxDynamicSharedMemorySize, (int)SMEM_ALIGN);

    proj_kernel<<<dim3(4, 16, 2), 256>>>(inputs, mems, Wq, Wc, bc);
    align_kernel<<<dim3(4, 32, 4), 256, SMEM_ALIGN>>>(mem_masks, v, pa);
    softmax_kernel<<<256, 256>>>(mem_masks, pa);
    ctx_kernel<<<dim3(4, 8, 4), 128>>>(mems, mem_masks, pa);
    out_kernel<<<dim3(8, 16, 3), 256>>>(inputs, Wout);
    reduce_kernel<<<(BN * TT * IND) / (256 * 4), 256>>>(bout, out);
}